// round 1
// baseline (speedup 1.0000x reference)
#include <cuda_runtime.h>

// ---------------------------------------------------------------------------
// Problem constants (all static per the reference):
//   B=32 sequences, H=16 heads, E=64, SEQLEN[i] = 256 + (37*i) % 257
//   out layout: concat over b of [H, L_b, L_b], scale = 1/sqrt(64) = 0.125
// ---------------------------------------------------------------------------
#define NB 32
#define NH 16
#define NE 64
#define BM 128
#define BN 128

struct Tables {
    int seqlen[NB];
    int tok_base[NB];      // prefix sum of L
    long long out_base[NB];// prefix sum of H*L^2
    int blk_base[NB + 1];  // prefix sum of H*ceil(L/128)^2
};

constexpr Tables make_tables() {
    Tables t{};
    int tb = 0;
    long long ob = 0;
    int bb = 0;
    for (int i = 0; i < NB; i++) {
        int L = 256 + (i * 37) % 257;
        t.seqlen[i] = L;
        t.tok_base[i] = tb;
        t.out_base[i] = ob;
        t.blk_base[i] = bb;
        int nt = (L + BM - 1) / BM;
        tb += L;
        ob += (long long)NH * L * L;
        bb += NH * nt * nt;
    }
    t.blk_base[NB] = bb;
    return t;
}

__constant__ Tables dtab = make_tables();

__global__ __launch_bounds__(256) void bmm1_kernel(
    const float* __restrict__ Q,
    const float* __restrict__ K,
    float* __restrict__ out)
{
    extern __shared__ float sm[];
    float* Qs = sm;            // [NE][BM] k-major (transposed)
    float* Ks = sm + NE * BM;  // [NE][BN] k-major (transposed)

    const int bid = blockIdx.x;

    // ---- locate (batch, head, qtile, ktile) via constant prefix table ----
    int b = 0;
#pragma unroll
    for (int i = 1; i < NB; i++) b += (bid >= dtab.blk_base[i]);
    const int L  = dtab.seqlen[b];
    const int nt = (L + BM - 1) / BM;
    int rem = bid - dtab.blk_base[b];
    const int h  = rem / (nt * nt);
    rem -= h * (nt * nt);
    const int qt = rem / nt;
    const int kt = rem - qt * nt;

    const int tid = threadIdx.x;
    const long long rowstride = (long long)NH * NE;  // 1024 floats per token
    const float* qbase = Q + (long long)dtab.tok_base[b] * rowstride + h * NE;
    const float* kbase = K + (long long)dtab.tok_base[b] * rowstride + h * NE;

    // ---- load both tiles, transposed into smem (k-major) ----
    // thread tid: m = tid & 127, k-group parity = tid >> 7.
    // Lanes within a warp cover consecutive m -> conflict-free STS.
    {
        const int m = tid & 127;
        const int kg0 = tid >> 7;  // 0 or 1

        const int qrow = qt * BM + m;
        const bool qv = qrow < L;
        const float* qsrc = qbase + (long long)qrow * rowstride;
#pragma unroll
        for (int j = 0; j < 8; j++) {
            const int kg = kg0 + 2 * j;  // 0..15
            float4 v = qv ? *(const float4*)(qsrc + kg * 4)
                          : make_float4(0.f, 0.f, 0.f, 0.f);
            Qs[(kg * 4 + 0) * BM + m] = v.x;
            Qs[(kg * 4 + 1) * BM + m] = v.y;
            Qs[(kg * 4 + 2) * BM + m] = v.z;
            Qs[(kg * 4 + 3) * BM + m] = v.w;
        }

        const int krow = kt * BN + m;
        const bool kv = krow < L;
        const float* ksrc = kbase + (long long)krow * rowstride;
#pragma unroll
        for (int j = 0; j < 8; j++) {
            const int kg = kg0 + 2 * j;
            float4 v = kv ? *(const float4*)(ksrc + kg * 4)
                          : make_float4(0.f, 0.f, 0.f, 0.f);
            Ks[(kg * 4 + 0) * BN + m] = v.x;
            Ks[(kg * 4 + 1) * BN + m] = v.y;
            Ks[(kg * 4 + 2) * BN + m] = v.z;
            Ks[(kg * 4 + 3) * BN + m] = v.w;
        }
    }
    __syncthreads();

    // ---- compute 8x8 micro-tile per thread ----
    const int tx = tid & 15;       // n direction
    const int ty = tid >> 4;       // m direction
    const int m0 = ty * 8;
    const int n0 = tx * 4;         // second n group at n0 + 64

    float acc[8][8];
#pragma unroll
    for (int i = 0; i < 8; i++)
#pragma unroll
        for (int j = 0; j < 8; j++) acc[i][j] = 0.f;

#pragma unroll 8
    for (int kk = 0; kk < NE; kk++) {
        float4 a0 = *(const float4*)&Qs[kk * BM + m0];
        float4 a1 = *(const float4*)&Qs[kk * BM + m0 + 4];
        float4 b0 = *(const float4*)&Ks[kk * BN + n0];
        float4 b1 = *(const float4*)&Ks[kk * BN + n0 + 64];
        float a[8] = {a0.x, a0.y, a0.z, a0.w, a1.x, a1.y, a1.z, a1.w};
        float bb[8] = {b0.x, b0.y, b0.z, b0.w, b1.x, b1.y, b1.z, b1.w};
#pragma unroll
        for (int i = 0; i < 8; i++)
#pragma unroll
            for (int j = 0; j < 8; j++) acc[i][j] = fmaf(a[i], bb[j], acc[i][j]);
    }

    // ---- epilogue: stage tile in smem (L can be odd -> vector STG to gmem
    //      would be misaligned), then fully-coalesced scalar global stores ----
    __syncthreads();  // done reading Qs/Ks; reuse the buffer as Os[BM*BN]
    float* Os = sm;
    const float scale = 0.125f;

#pragma unroll
    for (int i = 0; i < 8; i++) {
        float4 v0 = make_float4(acc[i][0] * scale, acc[i][1] * scale,
                                acc[i][2] * scale, acc[i][3] * scale);
        float4 v1 = make_float4(acc[i][4] * scale, acc[i][5] * scale,
                                acc[i][6] * scale, acc[i][7] * scale);
        *(float4*)&Os[(m0 + i) * BN + n0]      = v0;
        *(float4*)&Os[(m0 + i) * BN + n0 + 64] = v1;
    }
    __syncthreads();

    const long long obase = dtab.out_base[b] + (long long)h * L * L;
    const int q0 = qt * BM;
    const int n0g = kt * BN;

#pragma unroll 4
    for (int idx = tid; idx < BM * BN; idx += 256) {
        const int r = idx >> 7;
        const int c = idx & 127;
        const int q = q0 + r;
        const int n = n0g + c;
        if (q < L && n < L)
            out[obase + (long long)q * L + n] = Os[idx];
    }
}

extern "C" void kernel_launch(void* const* d_in, const int* in_sizes, int n_in,
                              void* d_out, int out_size)
{
    const float* q = (const float*)d_in[0];  // batch1 [NTOKENS, H*E] f32
    const float* k = (const float*)d_in[1];  // batch2 [NTOKENS, H*E] f32
    float* o = (float*)d_out;

    constexpr Tables ht = make_tables();
    const int nblocks = ht.blk_base[NB];     // exact tile count (5872)

    cudaFuncSetAttribute(bmm1_kernel,
                         cudaFuncAttributeMaxDynamicSharedMemorySize, 65536);
    bmm1_kernel<<<nblocks, 256, 65536>>>(q, k, o);
}

// round 2
// speedup vs baseline: 2.2161x; 2.2161x over previous
#include <cuda_runtime.h>
#include <cstdint>

// ---------------------------------------------------------------------------
// Ragged batched QK^T, all-static shapes:
//   B=32, H=16, E=64, SEQLEN[i] = 256 + (37*i) % 257, scale = 0.125
//   out = concat_b [H, L_b, L_b] flattened.
// TF32 tensor-core version (mma.sync m16n8k8), rna-rounded inputs.
// ---------------------------------------------------------------------------
#define NB 32
#define NH 16
#define NE 64
#define BM 128
#define BN 128
#define SMPAD 68   // floats per smem row (64 data + 4 pad) -> 272B = 17*16B

struct Tables {
    int seqlen[NB];
    int tok_base[NB];
    long long out_base[NB];
    int blk_base[NB + 1];
};

constexpr Tables make_tables() {
    Tables t{};
    int tb = 0; long long ob = 0; int bb = 0;
    for (int i = 0; i < NB; i++) {
        int L = 256 + (i * 37) % 257;
        t.seqlen[i] = L;
        t.tok_base[i] = tb;
        t.out_base[i] = ob;
        t.blk_base[i] = bb;
        int nt = (L + BM - 1) / BM;
        tb += L;
        ob += (long long)NH * L * L;
        bb += NH * nt * nt;
    }
    t.blk_base[NB] = bb;
    return t;
}

__constant__ Tables dtab = make_tables();

__device__ __forceinline__ uint32_t cvta_sm(const void* p) {
    uint32_t a;
    asm("{ .reg .u64 t; cvta.to.shared.u64 t, %1; cvt.u32.u64 %0, t; }"
        : "=r"(a) : "l"(p));
    return a;
}

__device__ __forceinline__ float to_tf32(float x) {
    float r;
    asm("cvt.rna.tf32.f32 %0, %1;" : "=f"(r) : "f"(x));
    return r;
}

__device__ __forceinline__ void ldm4(uint32_t* r, uint32_t addr) {
    asm volatile(
        "ldmatrix.sync.aligned.m8n8.x4.shared.b16 {%0,%1,%2,%3}, [%4];"
        : "=r"(r[0]), "=r"(r[1]), "=r"(r[2]), "=r"(r[3]) : "r"(addr));
}

__device__ __forceinline__ void mma_tf32(float* d, const uint32_t* a,
                                         uint32_t b0, uint32_t b1) {
    asm volatile(
        "mma.sync.aligned.m16n8k8.row.col.f32.tf32.tf32.f32 "
        "{%0,%1,%2,%3}, {%4,%5,%6,%7}, {%8,%9}, {%0,%1,%2,%3};"
        : "+f"(d[0]), "+f"(d[1]), "+f"(d[2]), "+f"(d[3])
        : "r"(a[0]), "r"(a[1]), "r"(a[2]), "r"(a[3]), "r"(b0), "r"(b1));
}

__global__ __launch_bounds__(256) void bmm1_tf32_kernel(
    const float* __restrict__ Q,
    const float* __restrict__ K,
    float* __restrict__ out)
{
    extern __shared__ float sm[];
    float* Qs = sm;                    // [128][SMPAD]
    float* Ks = sm + BM * SMPAD;       // [128][SMPAD]

    const int bid = blockIdx.x;

    // ---- locate (batch, head, qtile, ktile) ----
    int b = 0;
#pragma unroll
    for (int i = 1; i < NB; i++) b += (bid >= dtab.blk_base[i]);
    const int L  = dtab.seqlen[b];
    const int nt = (L + BM - 1) / BM;
    int rem = bid - dtab.blk_base[b];
    const int h  = rem / (nt * nt);
    rem -= h * (nt * nt);
    const int qt = rem / nt;
    const int kt = rem - qt * nt;

    const int tid = threadIdx.x;
    const long long rowstride = (long long)NH * NE;   // 1024 floats/token
    const float* qbase = Q + (long long)dtab.tok_base[b] * rowstride + h * NE;
    const float* kbase = K + (long long)dtab.tok_base[b] * rowstride + h * NE;

    // ---- global -> smem (tf32-rounded), [row][k] layout with pad ----
    {
        const int c4 = tid & 15;       // float4 column within row
        const int rl = tid >> 4;       // row within group of 16
#pragma unroll
        for (int g = 0; g < 8; g++) {
            const int m = rl + g * 16;
            const int qrow = qt * BM + m;
            float4 v = (qrow < L) ? *(const float4*)(qbase + (long long)qrow * rowstride + c4 * 4)
                                  : make_float4(0.f, 0.f, 0.f, 0.f);
            float4 w;
            w.x = to_tf32(v.x); w.y = to_tf32(v.y);
            w.z = to_tf32(v.z); w.w = to_tf32(v.w);
            *(float4*)&Qs[m * SMPAD + c4 * 4] = w;

            const int krow = kt * BN + m;
            float4 u = (krow < L) ? *(const float4*)(kbase + (long long)krow * rowstride + c4 * 4)
                                  : make_float4(0.f, 0.f, 0.f, 0.f);
            float4 x;
            x.x = to_tf32(u.x); x.y = to_tf32(u.y);
            x.z = to_tf32(u.z); x.w = to_tf32(u.w);
            *(float4*)&Ks[m * SMPAD + c4 * 4] = x;
        }
    }
    __syncthreads();

    // ---- warp layout: 8 warps = 4 (m) x 2 (n); warp tile 32m x 64n ----
    const int wid = tid >> 5;
    const int l   = tid & 31;
    const int wm  = wid & 3;
    const int wn  = wid >> 2;

    const uint32_t qs0 = cvta_sm(Qs);
    const uint32_t ks0 = cvta_sm(Ks);

    // A fragment pointers (ldmatrix x4 covers m16 x k8):
    //   lanes 0-7: m+0..7 @k0 | 8-15: m+8..15 @k0 | 16-23: m+0..7 @+16B | 24-31: m+8..15 @+16B
    const int arow = wm * 32 + (l & 7) + ((l >> 3) & 1) * 8;
    const int akoff = (l >> 4) * 16;
    uint32_t a_ptr0 = qs0 + arow * (SMPAD * 4) + akoff;
    uint32_t a_ptr1 = a_ptr0 + 16 * (SMPAD * 4);

    // B fragment pointers (ldmatrix x4 covers n16 x k8 = two n8 frags):
    //   lanes 0-7: n+0..7 @k0 | 8-15: n+0..7 @+16B | 16-23: n+8..15 @k0 | 24-31: n+8..15 @+16B
    const int brow = wn * 64 + (l & 7) + ((l >> 4) & 1) * 8;
    const int bkoff = ((l >> 3) & 1) * 16;
    uint32_t b_ptr[4];
#pragma unroll
    for (int j = 0; j < 4; j++)
        b_ptr[j] = ks0 + (brow + j * 16) * (SMPAD * 4) + bkoff;

    float acc[2][8][4];
#pragma unroll
    for (int mi = 0; mi < 2; mi++)
#pragma unroll
        for (int ni = 0; ni < 8; ni++)
#pragma unroll
            for (int r = 0; r < 4; r++) acc[mi][ni][r] = 0.f;

#pragma unroll
    for (int ks = 0; ks < 8; ks++) {
        const uint32_t koff = ks * 32;   // 8 tf32 = 32B per k-step
        uint32_t A0[4], A1[4], Bf[4][4];
        ldm4(A0, a_ptr0 + koff);
        ldm4(A1, a_ptr1 + koff);
#pragma unroll
        for (int j = 0; j < 4; j++) ldm4(Bf[j], b_ptr[j] + koff);

#pragma unroll
        for (int ni = 0; ni < 8; ni++) {
            const uint32_t b0 = Bf[ni >> 1][(ni & 1) * 2];
            const uint32_t b1 = Bf[ni >> 1][(ni & 1) * 2 + 1];
            mma_tf32(acc[0][ni], A0, b0, b1);
            mma_tf32(acc[1][ni], A1, b0, b1);
        }
    }

    // ---- epilogue: direct guarded global stores (32B-sector coalesced) ----
    const float sc = 0.125f;
    const long long obase = dtab.out_base[b] + (long long)h * L * L;
    const int q_base = qt * BM + wm * 32 + (l >> 2);
    const int n_base = kt * BN + wn * 64 + 2 * (l & 3);

#pragma unroll
    for (int mi = 0; mi < 2; mi++) {
#pragma unroll
        for (int h2 = 0; h2 < 2; h2++) {
            const int q = q_base + mi * 16 + h2 * 8;
            if (q >= L) continue;
            float* orow = out + obase + (long long)q * L;
#pragma unroll
            for (int ni = 0; ni < 8; ni++) {
                const int n = n_base + ni * 8;
                const float v0 = acc[mi][ni][h2 * 2 + 0] * sc;
                const float v1 = acc[mi][ni][h2 * 2 + 1] * sc;
                if (n < L)     orow[n]     = v0;
                if (n + 1 < L) orow[n + 1] = v1;
            }
        }
    }
}

extern "C" void kernel_launch(void* const* d_in, const int* in_sizes, int n_in,
                              void* d_out, int out_size)
{
    const float* q = (const float*)d_in[0];
    const float* k = (const float*)d_in[1];
    float* o = (float*)d_out;

    constexpr Tables ht = make_tables();
    const int nblocks = ht.blk_base[NB];

    constexpr int smem = 2 * BM * SMPAD * sizeof(float);  // 69632 B
    cudaFuncSetAttribute(bmm1_tf32_kernel,
                         cudaFuncAttributeMaxDynamicSharedMemorySize, smem);
    bmm1_tf32_kernel<<<nblocks, 256, smem>>>(q, k, o);
}